// round 7
// baseline (speedup 1.0000x reference)
#include <cuda_runtime.h>
#include <cuda_bf16.h>
#include <cstdint>
#include <cstddef>

// ============================================================================
// GCN 2-layer. CSR per-call (side stream), mma.sync bf16x3 GEMMs, fused tail.
//   h1 = x@W1 ; a1 = csr_agg(h1) ; h2 = relu(a1+b1)@W2 ;
//   out = log_softmax(csr_agg(h2) + b2)
// GEMMs: standard PTX mma.sync.m16n8k16 bf16 (sm_80+, legal on plain sm_103),
// hi/lo split (A=Ah+Al, B=Bh+Bl; AhBh+AhBl+AlBh in fp32) -> ~1e-6 rel err.
// ============================================================================

#define NN    100000
#define D1    128
#define D2    64
#define EMAX  1664000
#define SCAN_B 1024
#define NBLK  ((NN + SCAN_B - 1) / SCAN_B)   // 98

typedef unsigned long long u64;

__device__ float g_dinv[NN];
__device__ int   g_cnt[NN];
__device__ int   g_off[NN];
__device__ int   g_cur[NN];
__device__ int   g_bsum[128];
__device__ int2  g_edges[EMAX];              // {src, __float_as_int(w)}
__device__ float g_h1[(size_t)NN * D1];
__device__ float g_a1[(size_t)NN * D1];
__device__ float g_h2[(size_t)NN * D2];
__device__ int   g_is64;

// ---------------------------------------------------------------------------
// mma/ldmatrix helpers (standard PTX, sm_80+)
// ---------------------------------------------------------------------------
__device__ __forceinline__ uint32_t smem_to_u32(const void* p) {
    uint32_t a;
    asm("{ .reg .u64 t; cvta.to.shared.u64 t, %1; cvt.u32.u64 %0, t; }"
        : "=r"(a) : "l"(p));
    return a;
}
__device__ __forceinline__ void ldsm_x4(uint32_t* r, uint32_t addr) {
    asm volatile("ldmatrix.sync.aligned.m8n8.x4.shared.b16 {%0,%1,%2,%3}, [%4];"
                 : "=r"(r[0]), "=r"(r[1]), "=r"(r[2]), "=r"(r[3]) : "r"(addr));
}
__device__ __forceinline__ void mma16816(float* c, const uint32_t* a,
                                         const uint32_t* b) {
    asm volatile(
        "mma.sync.aligned.m16n8k16.row.col.f32.bf16.bf16.f32 "
        "{%0,%1,%2,%3}, {%4,%5,%6,%7}, {%8,%9}, {%0,%1,%2,%3};"
        : "+f"(c[0]), "+f"(c[1]), "+f"(c[2]), "+f"(c[3])
        : "r"(a[0]), "r"(a[1]), "r"(a[2]), "r"(a[3]), "r"(b[0]), "r"(b[1]));
}

// fp32 -> bf16 hi/lo split, two values packed per 32-bit word
__device__ __forceinline__ void split2(float a, float b, uint32_t& hi, uint32_t& lo) {
    __nv_bfloat16 ha = __float2bfloat16(a);
    __nv_bfloat16 hb = __float2bfloat16(b);
    __nv_bfloat16 la = __float2bfloat16(a - __bfloat162float(ha));
    __nv_bfloat16 lb = __float2bfloat16(b - __bfloat162float(hb));
    __nv_bfloat162 ph(ha, hb), pl(la, lb);
    hi = *(uint32_t*)&ph;
    lo = *(uint32_t*)&pl;
}

// ---------------------------------------------------------------------------
// Edge dtype detection
// ---------------------------------------------------------------------------
__global__ void detect_kernel(const int* __restrict__ e32) {
    int t = threadIdx.x;
    int nz = (e32[2 * t + 1] != 0) ? 1 : 0;
    int any = __syncthreads_or(nz);
    if (t == 0) g_is64 = (any == 0) ? 1 : 0;
}

__device__ __forceinline__ void load_edge(const void* __restrict__ ei, int e,
                                          int E, int& s, int& d) {
    if (g_is64) {
        const long long* p = (const long long*)ei;
        s = (int)p[e];
        d = (int)p[E + e];
    } else {
        const int* p = (const int*)ei;
        s = p[e];
        d = p[E + e];
    }
}

// ---------------------------------------------------------------------------
// CSR construction
// ---------------------------------------------------------------------------
__global__ void zero_cnt_kernel() {
    int i = blockIdx.x * blockDim.x + threadIdx.x;
    if (i < NN) g_cnt[i] = 0;
}
__global__ void hist_kernel(const void* __restrict__ ei, int E) {
    int e = blockIdx.x * blockDim.x + threadIdx.x;
    if (e >= E) return;
    int s, d;
    load_edge(ei, e, E, s, d);
    atomicAdd(&g_cnt[d], 1);
}
__global__ void dinv_kernel() {
    int i = blockIdx.x * blockDim.x + threadIdx.x;
    if (i < NN) g_dinv[i] = rsqrtf((float)(1 + g_cnt[i]));
}
__global__ void scan1_kernel() {
    __shared__ int sh[SCAN_B];
    int t = threadIdx.x;
    int i = blockIdx.x * SCAN_B + t;
    int v = (i < NN) ? g_cnt[i] : 0;
    sh[t] = v;
    __syncthreads();
#pragma unroll
    for (int o = 1; o < SCAN_B; o <<= 1) {
        int x = (t >= o) ? sh[t - o] : 0;
        __syncthreads();
        sh[t] += x;
        __syncthreads();
    }
    if (i < NN) g_off[i] = sh[t] - v;
    if (t == SCAN_B - 1) g_bsum[blockIdx.x] = sh[t];
}
__global__ void scan2_kernel(int nb) {
    __shared__ int sh[128];
    int t = threadIdx.x;
    int v = (t < nb) ? g_bsum[t] : 0;
    sh[t] = v;
    __syncthreads();
#pragma unroll
    for (int o = 1; o < 128; o <<= 1) {
        int x = (t >= o) ? sh[t - o] : 0;
        __syncthreads();
        sh[t] += x;
        __syncthreads();
    }
    if (t < nb) g_bsum[t] = sh[t] - v;
}
__global__ void scan3_kernel() {
    int i = blockIdx.x * blockDim.x + threadIdx.x;
    if (i >= NN) return;
    int o = g_off[i] + g_bsum[i >> 10];
    g_off[i] = o;
    g_cur[i] = o;
}
__global__ void fill_kernel(const void* __restrict__ ei, int E) {
    int e = blockIdx.x * blockDim.x + threadIdx.x;
    if (e >= E) return;
    int s, d;
    load_edge(ei, e, E, s, d);
    float w = g_dinv[s] * g_dinv[d];
    int pos = atomicAdd(&g_cur[d], 1);
    g_edges[pos] = make_int2(s, __float_as_int(w));
}

// ---------------------------------------------------------------------------
// bf16x3 tensor-core GEMM via mma.sync: C[M,N] = A[M,128] @ Bw[128,N]
// Per CTA: 128 (M) x N tile, K=128, 512 threads = 16 warps in a 4x4 grid
// (warp tile 32 x N/4). SMEM holds Ah/Al [128][136] and Bh/Bl [N][136]
// (B transposed to [n][k], 136-elem padded rows -> conflict-free ldmatrix).
// 3 passes: AhBh, AhBl, AlBh accumulated in fp32 fragments.
// Optionally A := relu(A + bias) during conversion.
// ---------------------------------------------------------------------------
template <int N, bool FUSE>
__global__ __launch_bounds__(512)
void mma_gemm_kernel(const float* __restrict__ A, const float* __restrict__ Bw,
                     const float* __restrict__ bias, float* __restrict__ C,
                     int M) {
    constexpr int SP  = 136;                 // padded row, elems
    constexpr int SPB = SP * 2;              // bytes (272)
    constexpr int OA_H = 0;
    constexpr int OA_L = 128 * SPB;
    constexpr int OB_H = 2 * 128 * SPB;
    constexpr int OB_L = OB_H + N * SPB;
    constexpr int MT = 2;                    // 16-row m-tiles per warp (32 rows)
    constexpr int NT = N / 32;               // 8-col n-tiles per warp (N/4 cols)
    static_assert(NT >= 2 && NT % 2 == 0, "NT pairs");

    extern __shared__ char smem[];
    const uint32_t sb = smem_to_u32(smem);
    const int tid = threadIdx.x;
    const int lane = tid & 31;
    const int wid = tid >> 5;
    const int m0 = blockIdx.x * 128;

    // --- load A -> Ah/Al (row-major [m][k], padded) ---
    for (int i = tid; i < 128 * 32; i += 512) {
        int row = i >> 5;
        int c4 = (i & 31) << 2;
        int gm = m0 + row;
        float4 v = make_float4(0.f, 0.f, 0.f, 0.f);
        if (gm < M) {
            v = *(const float4*)(A + (size_t)gm * 128 + c4);
            if constexpr (FUSE) {
                float4 bb = *(const float4*)(bias + c4);
                v.x = fmaxf(v.x + bb.x, 0.f);
                v.y = fmaxf(v.y + bb.y, 0.f);
                v.z = fmaxf(v.z + bb.z, 0.f);
                v.w = fmaxf(v.w + bb.w, 0.f);
            }
        }
        uint2 uh, ul;
        split2(v.x, v.y, uh.x, ul.x);
        split2(v.z, v.w, uh.y, ul.y);
        int off = row * SPB + c4 * 2;
        *(uint2*)(smem + OA_H + off) = uh;
        *(uint2*)(smem + OA_L + off) = ul;
    }

    // --- load B -> Bh/Bl transposed ([n][k], padded) ---
    for (int i = tid; i < 128 * N; i += 512) {
        int k = i / N;
        int n = i % N;
        float v = Bw[i];
        __nv_bfloat16 h = __float2bfloat16(v);
        __nv_bfloat16 l = __float2bfloat16(v - __bfloat162float(h));
        int off = n * SPB + k * 2;
        *(__nv_bfloat16*)(smem + OB_H + off) = h;
        *(__nv_bfloat16*)(smem + OB_L + off) = l;
    }
    __syncthreads();

    // --- compute ---
    const int wm = (wid & 3) * 32;           // warp m-offset
    const int wn = (wid >> 2) * (N / 4);     // warp n-offset

    // ldmatrix per-lane address components
    const uint32_t aLane = (uint32_t)(lane & 15) * SPB + ((lane >> 4) << 4);
    const uint32_t bLane = (uint32_t)((lane & 7) + ((lane >> 4) << 3)) * SPB
                         + (((lane >> 3) & 1) << 4);

    float c[MT][NT][4];
#pragma unroll
    for (int i = 0; i < MT; i++)
#pragma unroll
        for (int j = 0; j < NT; j++)
#pragma unroll
            for (int q = 0; q < 4; q++) c[i][j][q] = 0.f;

    const int aOff[3] = {OA_H, OA_H, OA_L};
    const int bOff[3] = {OB_H, OB_L, OB_H};

#pragma unroll
    for (int p = 0; p < 3; p++) {
        const uint32_t aB = sb + aOff[p] + (uint32_t)wm * SPB + aLane;
        const uint32_t bB = sb + bOff[p] + (uint32_t)wn * SPB + bLane;
#pragma unroll
        for (int ks = 0; ks < 8; ks++) {
            uint32_t af[MT][4];
#pragma unroll
            for (int i = 0; i < MT; i++)
                ldsm_x4(af[i], aB + (uint32_t)i * 16 * SPB + ks * 32);
            uint32_t bf[NT / 2][4];
#pragma unroll
            for (int j = 0; j < NT / 2; j++)
                ldsm_x4(bf[j], bB + (uint32_t)j * 16 * SPB + ks * 32);
#pragma unroll
            for (int i = 0; i < MT; i++)
#pragma unroll
                for (int j = 0; j < NT; j++)
                    mma16816(c[i][j], af[i], &bf[j >> 1][(j & 1) * 2]);
        }
    }

    // --- epilogue: c frag (row = t/4 [+8], col = 2*(t%4)) ---
    const int r0 = m0 + wm + (lane >> 2);
    const int cl = (lane & 3) * 2;
#pragma unroll
    for (int i = 0; i < MT; i++) {
        int row = r0 + i * 16;
#pragma unroll
        for (int j = 0; j < NT; j++) {
            int col = wn + j * 8 + cl;
            if (row < M)
                *(float2*)(C + (size_t)row * N + col) =
                    make_float2(c[i][j][0], c[i][j][1]);
            if (row + 8 < M)
                *(float2*)(C + (size_t)(row + 8) * N + col) =
                    make_float2(c[i][j][2], c[i][j][3]);
        }
    }
}

// ---------------------------------------------------------------------------
// CSR aggregation, layer 1: warp per dst node, lane owns float4 (128 dims).
// ---------------------------------------------------------------------------
__global__ void agg1_kernel(const float* __restrict__ h, float* __restrict__ a) {
    int node = (blockIdx.x * blockDim.x + threadIdx.x) >> 5;
    int lane = threadIdx.x & 31;
    if (node >= NN) return;
    int beg = g_off[node];
    int cnt = g_cnt[node];
    float di = g_dinv[node];
    float w0 = di * di;

    float4 acc = ((const float4*)(h + (size_t)node * D1))[lane];
    acc.x *= w0; acc.y *= w0; acc.z *= w0; acc.w *= w0;
    float4 acc2 = make_float4(0.f, 0.f, 0.f, 0.f);

    for (int base = 0; base < cnt; base += 32) {
        int rem = cnt - base;
        int m = rem < 32 ? rem : 32;
        int2 e = make_int2(0, 0);
        if (lane < m) e = g_edges[beg + base + lane];
        int j = 0;
        for (; j + 1 < m; j += 2) {
            int   s0  = __shfl_sync(0xffffffffu, e.x, j);
            float w_0 = __int_as_float(__shfl_sync(0xffffffffu, e.y, j));
            int   s1  = __shfl_sync(0xffffffffu, e.x, j + 1);
            float w_1 = __int_as_float(__shfl_sync(0xffffffffu, e.y, j + 1));
            float4 v0 = ((const float4*)(h + (size_t)s0 * D1))[lane];
            float4 v1 = ((const float4*)(h + (size_t)s1 * D1))[lane];
            acc.x  = fmaf(v0.x, w_0, acc.x);
            acc.y  = fmaf(v0.y, w_0, acc.y);
            acc.z  = fmaf(v0.z, w_0, acc.z);
            acc.w  = fmaf(v0.w, w_0, acc.w);
            acc2.x = fmaf(v1.x, w_1, acc2.x);
            acc2.y = fmaf(v1.y, w_1, acc2.y);
            acc2.z = fmaf(v1.z, w_1, acc2.z);
            acc2.w = fmaf(v1.w, w_1, acc2.w);
        }
        if (j < m) {
            int   s0  = __shfl_sync(0xffffffffu, e.x, j);
            float w_0 = __int_as_float(__shfl_sync(0xffffffffu, e.y, j));
            float4 v0 = ((const float4*)(h + (size_t)s0 * D1))[lane];
            acc.x = fmaf(v0.x, w_0, acc.x);
            acc.y = fmaf(v0.y, w_0, acc.y);
            acc.z = fmaf(v0.z, w_0, acc.z);
            acc.w = fmaf(v0.w, w_0, acc.w);
        }
    }
    acc.x += acc2.x; acc.y += acc2.y; acc.z += acc2.z; acc.w += acc2.w;
    ((float4*)(a + (size_t)node * D1))[lane] = acc;
}

// ---------------------------------------------------------------------------
// CSR aggregation layer 2 FUSED with bias + log_softmax.
// ---------------------------------------------------------------------------
__global__ void agg2_softmax_kernel(const float* __restrict__ h,
                                    const float* __restrict__ b2,
                                    float* __restrict__ out) {
    int node = (blockIdx.x * blockDim.x + threadIdx.x) >> 5;
    int lane = threadIdx.x & 31;
    if (node >= NN) return;
    int beg = g_off[node];
    int cnt = g_cnt[node];
    float di = g_dinv[node];
    float w0 = di * di;

    float2 acc = ((const float2*)(h + (size_t)node * D2))[lane];
    acc.x *= w0; acc.y *= w0;
    float2 acc2 = make_float2(0.f, 0.f);

    for (int base = 0; base < cnt; base += 32) {
        int rem = cnt - base;
        int m = rem < 32 ? rem : 32;
        int2 e = make_int2(0, 0);
        if (lane < m) e = g_edges[beg + base + lane];
        int j = 0;
        for (; j + 1 < m; j += 2) {
            int   s0  = __shfl_sync(0xffffffffu, e.x, j);
            float w_0 = __int_as_float(__shfl_sync(0xffffffffu, e.y, j));
            int   s1  = __shfl_sync(0xffffffffu, e.x, j + 1);
            float w_1 = __int_as_float(__shfl_sync(0xffffffffu, e.y, j + 1));
            float2 v0 = ((const float2*)(h + (size_t)s0 * D2))[lane];
            float2 v1 = ((const float2*)(h + (size_t)s1 * D2))[lane];
            acc.x  = fmaf(v0.x, w_0, acc.x);
            acc.y  = fmaf(v0.y, w_0, acc.y);
            acc2.x = fmaf(v1.x, w_1, acc2.x);
            acc2.y = fmaf(v1.y, w_1, acc2.y);
        }
        if (j < m) {
            int   s0  = __shfl_sync(0xffffffffu, e.x, j);
            float w_0 = __int_as_float(__shfl_sync(0xffffffffu, e.y, j));
            float2 v0 = ((const float2*)(h + (size_t)s0 * D2))[lane];
            acc.x = fmaf(v0.x, w_0, acc.x);
            acc.y = fmaf(v0.y, w_0, acc.y);
        }
    }
    float2 bb = ((const float2*)b2)[lane];
    float v0 = acc.x + acc2.x + bb.x;
    float v1 = acc.y + acc2.y + bb.y;
    float mx = fmaxf(v0, v1);
#pragma unroll
    for (int o = 16; o; o >>= 1) mx = fmaxf(mx, __shfl_xor_sync(0xffffffffu, mx, o));
    float s = expf(v0 - mx) + expf(v1 - mx);
#pragma unroll
    for (int o = 16; o; o >>= 1) s += __shfl_xor_sync(0xffffffffu, s, o);
    float ls = mx + logf(s);
    ((float2*)(out + (size_t)node * D2))[lane] = make_float2(v0 - ls, v1 - ls);
}

// ===========================================================================
// Launch
// ===========================================================================
static constexpr int SMEM_G1 = (2 * 128 + 2 * 128) * 272;  // 139264
static constexpr int SMEM_G2 = (2 * 128 + 2 * 64) * 272;   // 104448
static constexpr int GTILES  = (NN + 127) / 128;           // 782

extern "C" void kernel_launch(void* const* d_in, const int* in_sizes, int n_in,
                              void* d_out, int out_size) {
    const float* x  = (const float*)d_in[0];
    const void*  ei = d_in[1];
    const float* W1 = (const float*)d_in[2];
    const float* b1 = (const float*)d_in[3];
    const float* W2 = (const float*)d_in[4];
    const float* b2 = (const float*)d_in[5];
    float* out = (float*)d_out;

    const int E = in_sizes[1] / 2;

    float* h1 = nullptr; float* a1 = nullptr; float* h2 = nullptr;
    cudaGetSymbolAddress((void**)&h1, g_h1);
    cudaGetSymbolAddress((void**)&a1, g_a1);
    cudaGetSymbolAddress((void**)&h2, g_h2);

    // One-time setup on the uncaptured correctness call.
    static cudaStream_t side = nullptr;
    static cudaEvent_t evF = nullptr, evJ = nullptr;
    if (side == nullptr) {
        cudaStreamCreateWithFlags(&side, cudaStreamNonBlocking);
        cudaEventCreateWithFlags(&evF, cudaEventDisableTiming);
        cudaEventCreateWithFlags(&evJ, cudaEventDisableTiming);
        cudaFuncSetAttribute(mma_gemm_kernel<128, false>,
                             cudaFuncAttributeMaxDynamicSharedMemorySize, SMEM_G1);
        cudaFuncSetAttribute(mma_gemm_kernel<64, true>,
                             cudaFuncAttributeMaxDynamicSharedMemorySize, SMEM_G2);
    }

    // ---- fork: CSR build on side stream while GEMM1 runs on main ----
    cudaEventRecord(evF, 0);
    cudaStreamWaitEvent(side, evF, 0);

    detect_kernel<<<1, 1024, 0, side>>>((const int*)ei);
    zero_cnt_kernel<<<(NN + 255) / 256, 256, 0, side>>>();
    hist_kernel<<<(E + 255) / 256, 256, 0, side>>>(ei, E);
    dinv_kernel<<<(NN + 255) / 256, 256, 0, side>>>();
    scan1_kernel<<<NBLK, SCAN_B, 0, side>>>();
    scan2_kernel<<<1, 128, 0, side>>>(NBLK);
    scan3_kernel<<<(NN + 255) / 256, 256, 0, side>>>();
    fill_kernel<<<(E + 255) / 256, 256, 0, side>>>(ei, E);
    cudaEventRecord(evJ, side);

    // main: h1 = x @ W1  (mma.sync bf16x3)
    mma_gemm_kernel<128, false><<<GTILES, 512, SMEM_G1>>>(x, W1, nullptr, h1, NN);

    // ---- join ----
    cudaStreamWaitEvent(0, evJ, 0);

    // a1 = CSR aggregate of h1 (self loop folded)
    agg1_kernel<<<(NN * 32 + 255) / 256, 256>>>(h1, a1);

    // h2 = relu(a1 + b1) @ W2  (mma.sync bf16x3, fused bias+relu)
    mma_gemm_kernel<64, true><<<GTILES, 512, SMEM_G2>>>(a1, W2, b1, h2, NN);

    // out = log_softmax(CSR aggregate of h2 + b2)
    agg2_softmax_kernel<<<(NN * 32 + 255) / 256, 256>>>(h2, b2, out);
}

// round 10
// speedup vs baseline: 1.1537x; 1.1537x over previous
#include <cuda_runtime.h>
#include <cuda_fp16.h>
#include <cstdint>
#include <cstddef>

// ============================================================================
// GCN 2-layer. CSR per-call (side stream), f32x2 SGEMMs, fp16 gather features.
//   h1 = x@W1 (fp16 out) ; a1 = csr_agg(h1) fp32 ; h2 = relu(a1+b1)@W2 (fp16);
//   out = log_softmax(csr_agg(h2) + b2)
// Gathered features (h1, h2) stored fp16: halves edge-gather traffic; fp32
// accumulation keeps error ~1e-4 << 1e-3 gate.
// ============================================================================

#define NN    100000
#define D1    128
#define D2    64
#define EMAX  1664000
#define SCAN_B 1024
#define NBLK  ((NN + SCAN_B - 1) / SCAN_B)   // 98

typedef unsigned long long u64;

__device__ float  g_dinv[NN];
__device__ int    g_cnt[NN];
__device__ int    g_off[NN];
__device__ int    g_cur[NN];
__device__ int    g_bsum[128];
__device__ int2   g_edges[EMAX];             // {src, __float_as_int(w)}
__device__ __half g_h1[(size_t)NN * D1];     // fp16 gather features, layer 1
__device__ float  g_a1[(size_t)NN * D1];     // fp32 (GEMM2 operand)
__device__ __half g_h2[(size_t)NN * D2];     // fp16 gather features, layer 2
__device__ int    g_is64;

// ---------------------------------------------------------------------------
// f32x2 packed math (sm_100+)
// ---------------------------------------------------------------------------
__device__ __forceinline__ u64 pack2(float lo, float hi) {
    u64 r;
    asm("mov.b64 %0, {%1, %2};" : "=l"(r) : "f"(lo), "f"(hi));
    return r;
}
__device__ __forceinline__ void ffma2(u64& d, u64 a, u64 b) {
    asm("fma.rn.f32x2 %0, %1, %2, %0;" : "+l"(d) : "l"(a), "l"(b));
}
__device__ __forceinline__ float2 unpack2(u64 v) {
    float2 f;
    asm("mov.b64 {%0, %1}, %2;" : "=f"(f.x), "=f"(f.y) : "l"(v));
    return f;
}

// ---------------------------------------------------------------------------
// Edge dtype detection (int64 high words of nonneg < 2^31 are all zero)
// ---------------------------------------------------------------------------
__global__ void detect_kernel(const int* __restrict__ e32) {
    int t = threadIdx.x;
    int nz = (e32[2 * t + 1] != 0) ? 1 : 0;
    int any = __syncthreads_or(nz);
    if (t == 0) g_is64 = (any == 0) ? 1 : 0;
}

__device__ __forceinline__ void load_edge(const void* __restrict__ ei, int e,
                                          int E, int& s, int& d) {
    if (g_is64) {
        const long long* p = (const long long*)ei;
        s = (int)p[e];
        d = (int)p[E + e];
    } else {
        const int* p = (const int*)ei;
        s = p[e];
        d = p[E + e];
    }
}

// ---------------------------------------------------------------------------
// CSR construction
// ---------------------------------------------------------------------------
__global__ void zero_cnt_kernel() {
    int i = blockIdx.x * blockDim.x + threadIdx.x;
    if (i < NN) g_cnt[i] = 0;
}
__global__ void hist_kernel(const void* __restrict__ ei, int E) {
    int e = blockIdx.x * blockDim.x + threadIdx.x;
    if (e >= E) return;
    int s, d;
    load_edge(ei, e, E, s, d);
    atomicAdd(&g_cnt[d], 1);
}
__global__ void dinv_kernel() {
    int i = blockIdx.x * blockDim.x + threadIdx.x;
    if (i < NN) g_dinv[i] = rsqrtf((float)(1 + g_cnt[i]));
}
__global__ void scan1_kernel() {
    __shared__ int sh[SCAN_B];
    int t = threadIdx.x;
    int i = blockIdx.x * SCAN_B + t;
    int v = (i < NN) ? g_cnt[i] : 0;
    sh[t] = v;
    __syncthreads();
#pragma unroll
    for (int o = 1; o < SCAN_B; o <<= 1) {
        int x = (t >= o) ? sh[t - o] : 0;
        __syncthreads();
        sh[t] += x;
        __syncthreads();
    }
    if (i < NN) g_off[i] = sh[t] - v;
    if (t == SCAN_B - 1) g_bsum[blockIdx.x] = sh[t];
}
__global__ void scan2_kernel(int nb) {
    __shared__ int sh[128];
    int t = threadIdx.x;
    int v = (t < nb) ? g_bsum[t] : 0;
    sh[t] = v;
    __syncthreads();
#pragma unroll
    for (int o = 1; o < 128; o <<= 1) {
        int x = (t >= o) ? sh[t - o] : 0;
        __syncthreads();
        sh[t] += x;
        __syncthreads();
    }
    if (t < nb) g_bsum[t] = sh[t] - v;
}
__global__ void scan3_kernel() {
    int i = blockIdx.x * blockDim.x + threadIdx.x;
    if (i >= NN) return;
    int o = g_off[i] + g_bsum[i >> 10];
    g_off[i] = o;
    g_cur[i] = o;
}
__global__ void fill_kernel(const void* __restrict__ ei, int E) {
    int e = blockIdx.x * blockDim.x + threadIdx.x;
    if (e >= E) return;
    int s, d;
    load_edge(ei, e, E, s, d);
    float w = g_dinv[s] * g_dinv[d];
    int pos = atomicAdd(&g_cur[d], 1);
    g_edges[pos] = make_int2(s, __float_as_int(w));
}

// ---------------------------------------------------------------------------
// Pipelined, double-buffered SGEMM, f32x2 inner product, fp16 or fp32 output.
// C[M,N] = A[M,K] @ B[K,N]; optionally A := relu(A + bias[k]) on load.
// ---------------------------------------------------------------------------
template <int BM, int BN, int BK, int TM, int TN, bool FUSE_RELU_BIAS, bool HALF_OUT>
__global__ __launch_bounds__(256)
void sgemm_kernel(const float* __restrict__ A, const float* __restrict__ B,
                  const float* __restrict__ bias, void* __restrict__ Cv,
                  int M, int N, int K) {
    __shared__ float As[2][BK][BM + 4];
    __shared__ float Bs[2][BK][BN];

    constexpr int TX = BN / TN;
    static_assert((BM / TM) * TX == 256, "thread count");
    constexpr int KQ = BK / 4;
    constexpr int AQ = BM * BK / 4;
    constexpr int NQ = BN / 4;
    constexpr int BQ = BK * BN / 4;
    constexpr int TNH = TN / 2;
    constexpr int ALD = AQ / 256;
    constexpr int BLD = BQ / 256;
    static_assert(ALD * 256 == AQ && BLD * 256 == BQ, "exact split");

    const int tid = threadIdx.x;
    const int m0 = blockIdx.y * BM;
    const int n0 = blockIdx.x * BN;
    const int tx = tid % TX;
    const int ty = tid / TX;

    float4 ar[ALD];
    float4 br[BLD];

    u64 acc[TM][TNH];
#pragma unroll
    for (int i = 0; i < TM; i++)
#pragma unroll
        for (int j = 0; j < TNH; j++) acc[i][j] = 0ull;

    auto load_tiles = [&](int kt) {
#pragma unroll
        for (int u = 0; u < ALD; u++) {
            int i = tid + u * 256;
            int ml = i / KQ;
            int kq = i % KQ;
            int gm = m0 + ml;
            float4 v = make_float4(0.f, 0.f, 0.f, 0.f);
            if (gm < M) {
                v = *(const float4*)(A + (size_t)gm * K + kt + kq * 4);
                if (FUSE_RELU_BIAS) {
                    float4 bb = *(const float4*)(bias + kt + kq * 4);
                    v.x = fmaxf(v.x + bb.x, 0.f);
                    v.y = fmaxf(v.y + bb.y, 0.f);
                    v.z = fmaxf(v.z + bb.z, 0.f);
                    v.w = fmaxf(v.w + bb.w, 0.f);
                }
            }
            ar[u] = v;
        }
#pragma unroll
        for (int u = 0; u < BLD; u++) {
            int i = tid + u * 256;
            int kl = i / NQ;
            int nq = i % NQ;
            br[u] = *(const float4*)(B + (size_t)(kt + kl) * N + n0 + nq * 4);
        }
    };
    auto store_tiles = [&](int b) {
#pragma unroll
        for (int u = 0; u < ALD; u++) {
            int i = tid + u * 256;
            int ml = i / KQ;
            int kq = i % KQ;
            As[b][kq * 4 + 0][ml] = ar[u].x;
            As[b][kq * 4 + 1][ml] = ar[u].y;
            As[b][kq * 4 + 2][ml] = ar[u].z;
            As[b][kq * 4 + 3][ml] = ar[u].w;
        }
#pragma unroll
        for (int u = 0; u < BLD; u++) {
            int i = tid + u * 256;
            int kl = i / NQ;
            int nq = i % NQ;
            *(float4*)(&Bs[b][kl][nq * 4]) = br[u];
        }
    };

    load_tiles(0);
    store_tiles(0);
    __syncthreads();

    int buf = 0;
    for (int kt = 0; kt < K; kt += BK) {
        const int ktn = kt + BK;
        const bool has_next = ktn < K;
        if (has_next) load_tiles(ktn);

#pragma unroll
        for (int k = 0; k < BK; k++) {
            float a[TM];
#pragma unroll
            for (int i = 0; i < TM; i += 4)
                *(float4*)&a[i] = *(const float4*)&As[buf][k][ty * TM + i];
            u64 b2r[TNH];
#pragma unroll
            for (int j = 0; j < TNH; j++)       // native u64 pair loads: no movs
                b2r[j] = *(const u64*)&Bs[buf][k][tx * TN + 2 * j];
#pragma unroll
            for (int i = 0; i < TM; i++) {
                u64 a2 = pack2(a[i], a[i]);
#pragma unroll
                for (int j = 0; j < TNH; j++)
                    ffma2(acc[i][j], a2, b2r[j]);
            }
        }

        if (has_next) {
            store_tiles(buf ^ 1);
            __syncthreads();
            buf ^= 1;
        }
    }

    // ---- epilogue ----
#pragma unroll
    for (int i = 0; i < TM; i++) {
        int gm = m0 + ty * TM + i;
        if (gm < M) {
            if constexpr (HALF_OUT) {
                __half* Ch = (__half*)Cv;
                uint32_t hw[TNH];
#pragma unroll
                for (int j = 0; j < TNH; j++) {
                    float2 f = unpack2(acc[i][j]);
                    __half2 h2v = __floats2half2_rn(f.x, f.y);
                    hw[j] = *(uint32_t*)&h2v;
                }
                if constexpr (TNH == 4) {
                    uint4 v = make_uint4(hw[0], hw[1], hw[2], hw[3]);
                    *(uint4*)(Ch + (size_t)gm * N + n0 + tx * TN) = v;
                } else {
                    uint2 v = make_uint2(hw[0], hw[1]);
                    *(uint2*)(Ch + (size_t)gm * N + n0 + tx * TN) = v;
                }
            } else {
                float* Cf = (float*)Cv;
#pragma unroll
                for (int j = 0; j < TNH; j += 2) {
                    float2 f0 = unpack2(acc[i][j]);
                    float2 f1 = unpack2(acc[i][j + 1]);
                    float4 v = make_float4(f0.x, f0.y, f1.x, f1.y);
                    *(float4*)(Cf + (size_t)gm * N + n0 + tx * TN + 2 * j) = v;
                }
            }
        }
    }
}

// ---------------------------------------------------------------------------
// CSR aggregation, layer 1: warp per dst node, lane owns 4 dims (fp16 in,
// fp32 accumulate, fp32 out). Gather = uint2 (8B) per lane per edge.
// ---------------------------------------------------------------------------
__device__ __forceinline__ float4 h4_to_f4(uint2 u) {
    __half2 p0 = *(__half2*)&u.x;
    __half2 p1 = *(__half2*)&u.y;
    float2 f0 = __half22float2(p0);
    float2 f1 = __half22float2(p1);
    return make_float4(f0.x, f0.y, f1.x, f1.y);
}

__global__ void agg1_kernel(const __half* __restrict__ h, float* __restrict__ a) {
    int node = (blockIdx.x * blockDim.x + threadIdx.x) >> 5;
    int lane = threadIdx.x & 31;
    if (node >= NN) return;
    int beg = g_off[node];
    int cnt = g_cnt[node];
    float di = g_dinv[node];
    float w0 = di * di;

    float4 sv = h4_to_f4(((const uint2*)(h + (size_t)node * D1))[lane]);
    float4 acc = make_float4(sv.x * w0, sv.y * w0, sv.z * w0, sv.w * w0);
    float4 acc2 = make_float4(0.f, 0.f, 0.f, 0.f);

    for (int base = 0; base < cnt; base += 32) {
        int rem = cnt - base;
        int m = rem < 32 ? rem : 32;
        int2 e = make_int2(0, 0);
        if (lane < m) e = g_edges[beg + base + lane];
        int j = 0;
        for (; j + 1 < m; j += 2) {
            int   s0  = __shfl_sync(0xffffffffu, e.x, j);
            float w_0 = __int_as_float(__shfl_sync(0xffffffffu, e.y, j));
            int   s1  = __shfl_sync(0xffffffffu, e.x, j + 1);
            float w_1 = __int_as_float(__shfl_sync(0xffffffffu, e.y, j + 1));
            float4 v0 = h4_to_f4(((const uint2*)(h + (size_t)s0 * D1))[lane]);
            float4 v1 = h4_to_f4(((const uint2*)(h + (size_t)s1 * D1))[lane]);
            acc.x  = fmaf(v0.x, w_0, acc.x);
            acc.y  = fmaf(v0.y, w_0, acc.y);
            acc.z  = fmaf(v0.z, w_0, acc.z);
            acc.w  = fmaf(v0.w, w_0, acc.w);
            acc2.x = fmaf(v1.x, w_1, acc2.x);
            acc2.y = fmaf(v1.y, w_1, acc2.y);
            acc2.z = fmaf(v1.z, w_1, acc2.z);
            acc2.w = fmaf(v1.w, w_1, acc2.w);
        }
        if (j < m) {
            int   s0  = __shfl_sync(0xffffffffu, e.x, j);
            float w_0 = __int_as_float(__shfl_sync(0xffffffffu, e.y, j));
            float4 v0 = h4_to_f4(((const uint2*)(h + (size_t)s0 * D1))[lane]);
            acc.x = fmaf(v0.x, w_0, acc.x);
            acc.y = fmaf(v0.y, w_0, acc.y);
            acc.z = fmaf(v0.z, w_0, acc.z);
            acc.w = fmaf(v0.w, w_0, acc.w);
        }
    }
    acc.x += acc2.x; acc.y += acc2.y; acc.z += acc2.z; acc.w += acc2.w;
    ((float4*)(a + (size_t)node * D1))[lane] = acc;
}

// ---------------------------------------------------------------------------
// CSR aggregation layer 2 (fp16 gather) FUSED with bias + log_softmax.
// Lane owns dims (2*lane, 2*lane+1): one half2 (4B) per lane per edge.
// ---------------------------------------------------------------------------
__global__ void agg2_softmax_kernel(const __half* __restrict__ h,
                                    const float* __restrict__ b2,
                                    float* __restrict__ out) {
    int node = (blockIdx.x * blockDim.x + threadIdx.x) >> 5;
    int lane = threadIdx.x & 31;
    if (node >= NN) return;
    int beg = g_off[node];
    int cnt = g_cnt[node];
    float di = g_dinv[node];
    float w0 = di * di;

    float2 sv = __half22float2(((const __half2*)(h + (size_t)node * D2))[lane]);
    float2 acc = make_float2(sv.x * w0, sv.y * w0);
    float2 acc2 = make_float2(0.f, 0.f);

    for (int base = 0; base < cnt; base += 32) {
        int rem = cnt - base;
        int m = rem < 32 ? rem : 32;
        int2 e = make_int2(0, 0);
        if (lane < m) e = g_edges[beg + base + lane];
        int j = 0;
        for (; j + 1 < m; j += 2) {
            int   s0  = __shfl_sync(0xffffffffu, e.x, j);
            float w_0 = __int_as_float(__shfl_sync(0xffffffffu, e.y, j));
            int   s1  = __shfl_sync(0xffffffffu, e.x, j + 1);
            float w_1 = __int_as_float(__shfl_sync(0xffffffffu, e.y, j + 1));
            float2 v0 = __half22float2(((const __half2*)(h + (size_t)s0 * D2))[lane]);
            float2 v1 = __half22float2(((const __half2*)(h + (size_t)s1 * D2))[lane]);
            acc.x  = fmaf(v0.x, w_0, acc.x);
            acc.y  = fmaf(v0.y, w_0, acc.y);
            acc2.x = fmaf(v1.x, w_1, acc2.x);
            acc2.y = fmaf(v1.y, w_1, acc2.y);
        }
        if (j < m) {
            int   s0  = __shfl_sync(0xffffffffu, e.x, j);
            float w_0 = __int_as_float(__shfl_sync(0xffffffffu, e.y, j));
            float2 v0 = __half22float2(((const __half2*)(h + (size_t)s0 * D2))[lane]);
            acc.x = fmaf(v0.x, w_0, acc.x);
            acc.y = fmaf(v0.y, w_0, acc.y);
        }
    }
    float2 bb = ((const float2*)b2)[lane];
    float v0 = acc.x + acc2.x + bb.x;
    float v1 = acc.y + acc2.y + bb.y;
    float mx = fmaxf(v0, v1);
#pragma unroll
    for (int o = 16; o; o >>= 1) mx = fmaxf(mx, __shfl_xor_sync(0xffffffffu, mx, o));
    float s = expf(v0 - mx) + expf(v1 - mx);
#pragma unroll
    for (int o = 16; o; o >>= 1) s += __shfl_xor_sync(0xffffffffu, s, o);
    float ls = mx + logf(s);
    ((float2*)(out + (size_t)node * D2))[lane] = make_float2(v0 - ls, v1 - ls);
}

// ===========================================================================
// Launch: fork-join capture — CSR chain on side stream under GEMM1.
// ===========================================================================
extern "C" void kernel_launch(void* const* d_in, const int* in_sizes, int n_in,
                              void* d_out, int out_size) {
    const float* x  = (const float*)d_in[0];
    const void*  ei = d_in[1];
    const float* W1 = (const float*)d_in[2];
    const float* b1 = (const float*)d_in[3];
    const float* W2 = (const float*)d_in[4];
    const float* b2 = (const float*)d_in[5];
    float* out = (float*)d_out;

    const int E = in_sizes[1] / 2;

    __half* h1 = nullptr; float* a1 = nullptr; __half* h2 = nullptr;
    cudaGetSymbolAddress((void**)&h1, g_h1);
    cudaGetSymbolAddress((void**)&a1, g_a1);
    cudaGetSymbolAddress((void**)&h2, g_h2);

    static cudaStream_t side = nullptr;
    static cudaEvent_t evF = nullptr, evJ = nullptr;
    if (side == nullptr) {
        cudaStreamCreateWithFlags(&side, cudaStreamNonBlocking);
        cudaEventCreateWithFlags(&evF, cudaEventDisableTiming);
        cudaEventCreateWithFlags(&evJ, cudaEventDisableTiming);
    }

    // ---- fork: CSR build on side stream while GEMM1 runs on main ----
    cudaEventRecord(evF, 0);
    cudaStreamWaitEvent(side, evF, 0);

    detect_kernel<<<1, 1024, 0, side>>>((const int*)ei);
    zero_cnt_kernel<<<(NN + 255) / 256, 256, 0, side>>>();
    hist_kernel<<<(E + 255) / 256, 256, 0, side>>>(ei, E);
    dinv_kernel<<<(NN + 255) / 256, 256, 0, side>>>();
    scan1_kernel<<<NBLK, SCAN_B, 0, side>>>();
    scan2_kernel<<<1, 128, 0, side>>>(NBLK);
    scan3_kernel<<<(NN + 255) / 256, 256, 0, side>>>();
    fill_kernel<<<(E + 255) / 256, 256, 0, side>>>(ei, E);
    cudaEventRecord(evJ, side);

    // main: h1 = x @ W1   (M=NN, N=128, K=128), fp16 out
    {
        dim3 grid(D1 / 128, (NN + 127) / 128);
        sgemm_kernel<128, 128, 16, 8, 8, false, true><<<grid, 256>>>(
            x, W1, nullptr, h1, NN, D1, D1);
    }

    // ---- join ----
    cudaStreamWaitEvent(0, evJ, 0);

    // a1 = CSR aggregate of h1 (fp16 gather, fp32 out; self loop folded)
    agg1_kernel<<<(NN * 32 + 255) / 256, 256>>>(h1, a1);

    // h2 = relu(a1 + b1) @ W2   (M=NN, N=64, K=128), fp16 out
    {
        dim3 grid(D2 / 64, (NN + 127) / 128);
        sgemm_kernel<128, 64, 16, 8, 4, true, true><<<grid, 256>>>(
            a1, W2, b1, h2, NN, D2, D1);
    }

    // out = log_softmax(CSR aggregate of h2 + b2)  -- fused
    agg2_softmax_kernel<<<(NN * 32 + 255) / 256, 256>>>(h2, b2, out);
}